// round 12
// baseline (speedup 1.0000x reference)
#include <cuda_runtime.h>
#include <math.h>

#define CUTOFF   1.5f
#define NMAX     16384
#define NCCAP    15
#define NCMAX    (NCCAP*NCCAP*NCCAP + 9)   // 3384
#define NCLAUNCH (NCCAP*NCCAP*NCCAP)       // 3375 force blocks
#define CAP      24                         // max atoms per cell (binning)
#define MAXCAND  256                        // staged candidates per cell-block
#define FBLK     64                         // force block: 2 warps

// ---------------- device scratch (no allocations allowed) ----------------
__device__ float        g_cellm[9];          // cell matrix (rows = lattice vectors)
__device__ int          g_nc[3];
__device__ int          g_count[NCMAX];      // zero at entry (static init / reset)
__device__ float4       g_cpos[NCMAX*CAP];   // per-cell atoms: xyz, w = 8*origIdx + spec
__device__ float4       g_tbl[64];           // (1/sig, eps/alp, alp-1, eps/sig)
__device__ float        g_sig2[64];          // sig^2
__device__ float        g_part[4096];        // per-block energy partials
__device__ unsigned int g_done = 0u;         // reset by last force block

// =======================================================================
// k_bin: tables + cell setup + bin atoms into padded cell lists.
// =======================================================================
__global__ void __launch_bounds__(128) k_bin(
    const float* __restrict__ pos, const float* __restrict__ cell,
    const float* __restrict__ sig, const float* __restrict__ eps,
    const float* __restrict__ alp, const int* __restrict__ spec,
    int n, int S)
{
    int i = blockIdx.x * blockDim.x + threadIdx.x;

    if (blockIdx.x == 0 && threadIdx.x < S*S) {
        int t = threadIdx.x;
        float sg = sig[t], ep = eps[t], al = alp[t];
        g_tbl[t]  = make_float4(1.0f/sg, ep/al, al - 1.0f, ep/sg);
        g_sig2[t] = sg * sg;
    }

    float c00=cell[0], c01=cell[1], c02=cell[2];
    float c10=cell[3], c11=cell[4], c12=cell[5];
    float c20=cell[6], c21=cell[7], c22=cell[8];
    float det = c00*(c11*c22 - c12*c21) - c01*(c10*c22 - c12*c20) + c02*(c10*c21 - c11*c20);
    float id = 1.0f / det;
    float i00=(c11*c22-c12*c21)*id, i01=(c02*c21-c01*c22)*id, i02=(c01*c12-c02*c11)*id;
    float i10=(c12*c20-c10*c22)*id, i11=(c00*c22-c02*c20)*id, i12=(c02*c10-c00*c12)*id;
    float i20=(c10*c21-c11*c20)*id, i21=(c01*c20-c00*c21)*id, i22=(c00*c11-c01*c10)*id;
    float w0 = rsqrtf(i00*i00 + i10*i10 + i20*i20);
    float w1 = rsqrtf(i01*i01 + i11*i11 + i21*i21);
    float w2 = rsqrtf(i02*i02 + i12*i12 + i22*i22);
    int n0 = (int)floorf(w0 / CUTOFF); n0 = n0 < 1 ? 1 : (n0 > NCCAP ? NCCAP : n0);
    int n1 = (int)floorf(w1 / CUTOFF); n1 = n1 < 1 ? 1 : (n1 > NCCAP ? NCCAP : n1);
    int n2 = (int)floorf(w2 / CUTOFF); n2 = n2 < 1 ? 1 : (n2 > NCCAP ? NCCAP : n2);

    if (i == 0) {
        g_cellm[0]=c00; g_cellm[1]=c01; g_cellm[2]=c02;
        g_cellm[3]=c10; g_cellm[4]=c11; g_cellm[5]=c12;
        g_cellm[6]=c20; g_cellm[7]=c21; g_cellm[8]=c22;
        g_nc[0]=n0; g_nc[1]=n1; g_nc[2]=n2;
    }

    if (i < n) {
        float x = pos[3*i], y = pos[3*i+1], z = pos[3*i+2];
        float f0 = x*i00 + y*i10 + z*i20;
        float f1 = x*i01 + y*i11 + z*i21;
        float f2 = x*i02 + y*i12 + z*i22;
        f0 -= floorf(f0); f1 -= floorf(f1); f2 -= floorf(f2);
        int a = (int)(f0 * (float)n0); a = a >= n0 ? n0-1 : (a < 0 ? 0 : a);
        int b = (int)(f1 * (float)n1); b = b >= n1 ? n1-1 : (b < 0 ? 0 : b);
        int c = (int)(f2 * (float)n2); c = c >= n2 ? n2-1 : (c < 0 ? 0 : c);
        int cid = (c*n1 + b)*n0 + a;
        int r = atomicAdd(&g_count[cid], 1);
        if (r < CAP)
            g_cpos[cid*CAP + r] = make_float4(x, y, z, (float)(8*i + spec[i]));
    }
}

// =======================================================================
// k_force: ONE 64-THREAD BLOCK PER CELL.
//   warp0: 27-neighborhood setup (wrap/shift/count/scan) once per cell
//   all:   stage ~84 shifted candidates compactly into shared
//   both warps: loop home atoms (warp-strided), lanes sweep staged list
//   energy reduced once per warp; g_part + ticket finalize.
// =======================================================================
__global__ void __launch_bounds__(FBLK) k_force(
    float* __restrict__ out, int n, int S)
{
    __shared__ float4 s_tbl[64];
    __shared__ float  s_sig2[64];
    __shared__ float4 s_cand[MAXCAND];
    __shared__ float4 s_sh[27];
    __shared__ int    s_cb[27], s_cn[27], s_off[28];
    __shared__ float  s_e[2];
    __shared__ int    s_flag;

    int t = threadIdx.x, lane = t & 31, warp = t >> 5;
    if (t < S*S) { s_tbl[t] = g_tbl[t]; s_sig2[t] = g_sig2[t]; }

    int ncx = g_nc[0], ncy = g_nc[1], ncz = g_nc[2];
    int nctot = ncx*ncy*ncz;
    int cid = blockIdx.x;
    float blk_e = 0.0f;

    if (cid < nctot) {
        // ---- neighborhood setup (warp 0) ----
        if (warp == 0) {
            int cnt = 0;
            if (lane < 27) {
                int cx = cid % ncx, cy = (cid / ncx) % ncy, cz = cid / (ncx*ncy);
                int ox = lane % 3 - 1, oy = (lane / 3) % 3 - 1, oz = lane / 9 - 1;
                int rx = cx + ox, ry = cy + oy, rz = cz + oz;
                int wx = 0, wy = 0, wz = 0;
                if (rx < 0) { rx += ncx; wx = -1; } else if (rx >= ncx) { rx -= ncx; wx = 1; }
                if (ry < 0) { ry += ncy; wy = -1; } else if (ry >= ncy) { ry -= ncy; wy = 1; }
                if (rz < 0) { rz += ncz; wz = -1; } else if (rz >= ncz) { rz -= ncz; wz = 1; }
                float shx = wx*g_cellm[0] + wy*g_cellm[3] + wz*g_cellm[6];
                float shy = wx*g_cellm[1] + wy*g_cellm[4] + wz*g_cellm[7];
                float shz = wx*g_cellm[2] + wy*g_cellm[5] + wz*g_cellm[8];
                int cidn = (rz*ncy + ry)*ncx + rx;
                cnt = g_count[cidn];
                cnt = cnt > CAP ? CAP : cnt;
                s_cb[lane] = cidn * CAP;
                s_cn[lane] = cnt;
                s_sh[lane] = make_float4(shx, shy, shz, 0.0f);
            }
            int inc = cnt;
            #pragma unroll
            for (int o = 1; o < 32; o <<= 1) {
                int x = __shfl_up_sync(0xffffffffu, inc, o);
                if (lane >= o) inc += x;
            }
            int tot = __shfl_sync(0xffffffffu, inc, 26);
            if (lane < 27) s_off[lane] = inc - cnt;
            if (lane == 0) s_off[27] = tot > MAXCAND ? MAXCAND : tot;
        }
        __syncthreads();

        int ntot = s_off[27];

        // ---- stage shifted candidates: thread t -> (cell t/2, slot t%2, stride 2)
        if (t < 54) {
            int j = t >> 1;
            int cnt = s_cn[j], cb = s_cb[j], off = s_off[j];
            float4 sh = s_sh[j];
            for (int k = t & 1; k < cnt; k += 2) {
                int q = off + k;
                if (q < MAXCAND) {
                    float4 p = g_cpos[cb + k];
                    s_cand[q] = make_float4(p.x + sh.x, p.y + sh.y, p.z + sh.z, p.w);
                }
            }
        }
        __syncthreads();

        // ---- compute: warps stride over home atoms; lanes sweep staged list
        int nhome = s_cn[13], hoff = s_off[13];
        float en = 0.0f;
        for (int ai = warp; ai < nhome; ai += 2) {
            float4 ha = s_cand[hoff + ai];
            int hw = (int)ha.w;
            int sBase = (hw & 7) * S;
            int orig  = hw >> 3;
            float fx = 0.f, fy = 0.f, fz = 0.f;
            for (int q = lane; q < ntot; q += 32) {   // no collectives inside
                float4 cb = s_cand[q];
                float dx = cb.x - ha.x;
                float dy = cb.y - ha.y;
                float dz = cb.z - ha.z;
                float r2 = fmaf(dx,dx, fmaf(dy,dy, dz*dz));
                int idx = sBase + ((int)cb.w & 7);
                if (r2 < s_sig2[idx] && r2 > 1e-12f) {
                    float rinv = rsqrtf(r2);
                    float r = r2 * rinv;
                    float4 tb = s_tbl[idx];
                    float f = fmaf(-r, tb.x, 1.0f);      // 1 - r/sig
                    float pw = __powf(f, tb.z);          // f^(alpha-1)
                    en = fmaf(tb.y * f, pw, en);         // eps/alpha * f^alpha
                    float coef = tb.w * pw * rinv;       // eps/sig * f^(a-1) / r
                    fx = fmaf(coef, dx, fx);
                    fy = fmaf(coef, dy, fy);
                    fz = fmaf(coef, dz, fz);
                }
            }
            // per-home-atom force reduction (warp-uniform trip count)
            #pragma unroll
            for (int o = 16; o; o >>= 1) {
                fx += __shfl_down_sync(0xffffffffu, fx, o);
                fy += __shfl_down_sync(0xffffffffu, fy, o);
                fz += __shfl_down_sync(0xffffffffu, fz, o);
            }
            if (lane == 0) {                      // F_i = -sum coef*(r_j - r_i)
                out[1 + 3*orig + 0] = -fx;
                out[1 + 3*orig + 1] = -fy;
                out[1 + 3*orig + 2] = -fz;
            }
        }
        // energy: reduce once per warp
        #pragma unroll
        for (int o = 16; o; o >>= 1)
            en += __shfl_down_sync(0xffffffffu, en, o);
        if (lane == 0) s_e[warp] = en;
        __syncthreads();
        if (t == 0) blk_e = s_e[0] + s_e[1];
    }

    // ---- energy partial + last-block finalize (ALL blocks participate) ----
    if (t == 0) {
        g_part[blockIdx.x] = blk_e;
        __threadfence();
        unsigned int d = atomicAdd(&g_done, 1u);
        s_flag = (d == gridDim.x - 1) ? 1 : 0;
    }
    __syncthreads();

    if (s_flag) {
        __threadfence();
        int nb = gridDim.x;
        float acc = 0.f;
        for (int k = t; k < nb; k += FBLK) acc += g_part[k];
        __shared__ float s_red[FBLK];
        s_red[t] = acc;
        __syncthreads();
        for (int o = FBLK/2; o > 0; o >>= 1) {
            if (t < o) s_red[t] += s_red[t + o];
            __syncthreads();
        }
        if (t == 0) {
            out[0] = 0.5f * s_red[0];
            g_done = 0u;
        }
        for (int k = t; k < NCMAX; k += FBLK) g_count[k] = 0;
    }
}

// ---------------- launch ----------------
extern "C" void kernel_launch(void* const* d_in, const int* in_sizes, int n_in,
                              void* d_out, int out_size) {
    const float* pos  = (const float*)d_in[0];
    const float* cell = (const float*)d_in[1];
    const float* sig  = (const float*)d_in[2];
    const float* eps  = (const float*)d_in[3];
    const float* alp  = (const float*)d_in[4];
    const int*   spec = (const int*)  d_in[5];
    int n  = in_sizes[5];
    int ss = in_sizes[2];
    int S = 1; while (S*S < ss) S++;
    float* out = (float*)d_out;

    k_bin<<<(n + 127)/128, 128>>>(pos, cell, sig, eps, alp, spec, n, S);
    k_force<<<NCLAUNCH, FBLK>>>(out, n, S);
}

// round 13
// speedup vs baseline: 1.2592x; 1.2592x over previous
#include <cuda_runtime.h>
#include <math.h>

#define CUTOFF   1.5f
#define NMAX     16384
#define NCCAP    15
#define NCMAX    (NCCAP*NCCAP*NCCAP + 9)   // 3384
#define CAP      24                         // max atoms per cell
#define FBLK     128                        // force block threads (4 warps, 2 atoms)

// ---------------- device scratch (no allocations allowed) ----------------
__device__ float        g_cellm[9];          // cell matrix (rows = lattice vectors)
__device__ int          g_nc[3];
__device__ int          g_count[NCMAX];      // MUST be zero at kernel_launch entry
__device__ float4       g_cpos[NCMAX*CAP];   // padded per-cell atom lists (xyz + species)
__device__ float4       g_apos[NMAX];        // per-atom: xyz, w = spec + 8*(cx+16*cy+256*cz)
__device__ float4       g_tbl[64];           // (1/sig, eps/alp, alp-1, eps/sig)
__device__ float        g_sig2[64];          // sig^2
__device__ float        g_part[4096];        // per-block energy partials
__device__ unsigned int g_done = 0u;         // reset by last force block

// =======================================================================
// k_bin: tables + cell setup + bin atoms into padded cell lists.
// =======================================================================
__global__ void __launch_bounds__(128) k_bin(
    const float* __restrict__ pos, const float* __restrict__ cell,
    const float* __restrict__ sig, const float* __restrict__ eps,
    const float* __restrict__ alp, const int* __restrict__ spec,
    int n, int S)
{
    int i = blockIdx.x * blockDim.x + threadIdx.x;

    if (blockIdx.x == 0 && threadIdx.x < S*S) {
        int t = threadIdx.x;
        float sg = sig[t], ep = eps[t], al = alp[t];
        g_tbl[t]  = make_float4(1.0f/sg, ep/al, al - 1.0f, ep/sg);
        g_sig2[t] = sg * sg;
    }

    float c00=cell[0], c01=cell[1], c02=cell[2];
    float c10=cell[3], c11=cell[4], c12=cell[5];
    float c20=cell[6], c21=cell[7], c22=cell[8];
    float det = c00*(c11*c22 - c12*c21) - c01*(c10*c22 - c12*c20) + c02*(c10*c21 - c11*c20);
    float id = 1.0f / det;
    float i00=(c11*c22-c12*c21)*id, i01=(c02*c21-c01*c22)*id, i02=(c01*c12-c02*c11)*id;
    float i10=(c12*c20-c10*c22)*id, i11=(c00*c22-c02*c20)*id, i12=(c02*c10-c00*c12)*id;
    float i20=(c10*c21-c11*c20)*id, i21=(c01*c20-c00*c21)*id, i22=(c00*c11-c01*c10)*id;
    float w0 = rsqrtf(i00*i00 + i10*i10 + i20*i20);
    float w1 = rsqrtf(i01*i01 + i11*i11 + i21*i21);
    float w2 = rsqrtf(i02*i02 + i12*i12 + i22*i22);
    int n0 = (int)floorf(w0 / CUTOFF); n0 = n0 < 1 ? 1 : (n0 > NCCAP ? NCCAP : n0);
    int n1 = (int)floorf(w1 / CUTOFF); n1 = n1 < 1 ? 1 : (n1 > NCCAP ? NCCAP : n1);
    int n2 = (int)floorf(w2 / CUTOFF); n2 = n2 < 1 ? 1 : (n2 > NCCAP ? NCCAP : n2);

    if (i == 0) {
        g_cellm[0]=c00; g_cellm[1]=c01; g_cellm[2]=c02;
        g_cellm[3]=c10; g_cellm[4]=c11; g_cellm[5]=c12;
        g_cellm[6]=c20; g_cellm[7]=c21; g_cellm[8]=c22;
        g_nc[0]=n0; g_nc[1]=n1; g_nc[2]=n2;
    }

    if (i < n) {
        float x = pos[3*i], y = pos[3*i+1], z = pos[3*i+2];
        float f0 = x*i00 + y*i10 + z*i20;
        float f1 = x*i01 + y*i11 + z*i21;
        float f2 = x*i02 + y*i12 + z*i22;
        f0 -= floorf(f0); f1 -= floorf(f1); f2 -= floorf(f2);
        int a = (int)(f0 * (float)n0); a = a >= n0 ? n0-1 : (a < 0 ? 0 : a);
        int b = (int)(f1 * (float)n1); b = b >= n1 ? n1-1 : (b < 0 ? 0 : b);
        int c = (int)(f2 * (float)n2); c = c >= n2 ? n2-1 : (c < 0 ? 0 : c);
        int cid = (c*n1 + b)*n0 + a;
        int sp = spec[i];
        g_apos[i] = make_float4(x, y, z, (float)(sp + 8*(a + 16*b + 256*c)));
        int r = atomicAdd(&g_count[cid], 1);
        if (r < CAP)
            g_cpos[cid*CAP + r] = make_float4(x, y, z, (float)sp);
    }
}

// =======================================================================
// k_force: TWO half-warps per atom (cells 0-13 / 14-26), 2 slots per cell.
// Latency-chain optimized: speculative first candidate load issued in
// parallel with the count load; one-deep register prefetch in the loop.
// =======================================================================
__global__ void __launch_bounds__(FBLK) k_force(
    float* __restrict__ out, int n, int S)
{
    __shared__ float4 s_tbl[64];
    __shared__ float  s_sig2[64];
    __shared__ float4 s_f[FBLK/32];
    __shared__ int    s_flag;

    int t = threadIdx.x, lane = t & 31, warp = t >> 5;
    if (t < S*S) { s_tbl[t] = g_tbl[t]; s_sig2[t] = g_sig2[t]; }
    __syncthreads();

    int aslot = blockIdx.x * (FBLK/32) + warp;
    int a = aslot >> 1;          // atom index
    int h = aslot & 1;           // half: 0 -> cells 0..13, 1 -> cells 14..26
    float fx = 0.f, fy = 0.f, fz = 0.f, en = 0.f;

    if (a < n) {
        float4 pa = __ldg(&g_apos[a]);
        int w  = (int)pa.w;
        int si = w & 7;
        int pk = w >> 3;
        int cx = pk & 15, cy = (pk >> 4) & 15, cz = pk >> 8;
        int ncx = g_nc[0], ncy = g_nc[1], ncz = g_nc[2];

        // lane -> (local cell, slot) without runtime division
        int ncell = h ? 13 : 14;
        bool act  = lane < 2*ncell;
        int li    = (lane < ncell) ? lane : (lane - ncell);
        int slot  = (lane < ncell) ? 0 : 1;
        int c     = h * 14 + li;                // 0..26

        int cnt = 0, cbase = 0;
        float bx = 0.f, by = 0.f, bz = 0.f;
        float4 pb0 = make_float4(0.f, 0.f, 0.f, 0.f);
        if (act) {
            int ox = c % 3 - 1;
            int oy = (c / 3) % 3 - 1;
            int oz = c / 9 - 1;
            int rx = cx + ox, ry = cy + oy, rz = cz + oz;
            int wx = 0, wy = 0, wz = 0;
            if (rx < 0) { rx += ncx; wx = -1; } else if (rx >= ncx) { rx -= ncx; wx = 1; }
            if (ry < 0) { ry += ncy; wy = -1; } else if (ry >= ncy) { ry -= ncy; wy = 1; }
            if (rz < 0) { rz += ncz; wz = -1; } else if (rz >= ncz) { rz -= ncz; wz = 1; }
            int cidn = (rz*ncy + ry)*ncx + rx;
            cbase = cidn * CAP;
            // issue BOTH loads back-to-back: count and speculative first candidate
            cnt = __ldg(&g_count[cidn]);
            pb0 = __ldg(&g_cpos[cbase + slot]);   // in-bounds always; discarded if slot>=cnt
            bx = wx*g_cellm[0] + wy*g_cellm[3] + wz*g_cellm[6] - pa.x;
            by = wx*g_cellm[1] + wy*g_cellm[4] + wz*g_cellm[7] - pa.y;
            bz = wx*g_cellm[2] + wy*g_cellm[5] + wz*g_cellm[8] - pa.z;
            cnt = cnt > CAP ? CAP : cnt;
        }

        int sBase = si * S;
        int m = slot;
        if (act && m < cnt) {
            float4 pb = pb0;
            for (;;) {
                int mn = m + 2;
                bool more = mn < cnt;
                float4 pn;
                if (more) pn = __ldg(&g_cpos[cbase + mn]);   // prefetch before body
                float dx = pb.x + bx;
                float dy = pb.y + by;
                float dz = pb.z + bz;
                float r2 = fmaf(dx,dx, fmaf(dy,dy, dz*dz));
                int idx = sBase + (int)pb.w;
                // r2 < sig^2  <=>  1 - r/sig > 0  (implies r < cutoff)
                if (r2 < s_sig2[idx] && r2 > 1e-12f) {
                    float rinv = rsqrtf(r2);
                    float r = r2 * rinv;
                    float4 tb = s_tbl[idx];
                    float f = fmaf(-r, tb.x, 1.0f);          // 1 - r/sig
                    float pw = __powf(f, tb.z);              // f^(alpha-1)
                    en = fmaf(tb.y * f, pw, en);             // eps/alpha * f^alpha
                    float coef = tb.w * pw * rinv;           // eps/sig * f^(a-1) / r
                    fx = fmaf(-coef, dx, fx);
                    fy = fmaf(-coef, dy, fy);
                    fz = fmaf(-coef, dz, fz);
                }
                if (!more) break;
                pb = pn; m = mn;
            }
        }
    }

    // warp reduction
    #pragma unroll
    for (int off = 16; off; off >>= 1) {
        fx += __shfl_down_sync(0xffffffffu, fx, off);
        fy += __shfl_down_sync(0xffffffffu, fy, off);
        fz += __shfl_down_sync(0xffffffffu, fz, off);
        en += __shfl_down_sync(0xffffffffu, en, off);
    }
    if (lane == 0) s_f[warp] = make_float4(fx, fy, fz, en);
    __syncthreads();

    // combine half-warp pairs -> per-atom force
    if (t < FBLK/64) {
        int aa = blockIdx.x * (FBLK/64) + t;
        if (aa < n) {
            float4 u = s_f[2*t], v = s_f[2*t+1];
            out[1 + 3*aa + 0] = u.x + v.x;
            out[1 + 3*aa + 1] = u.y + v.y;
            out[1 + 3*aa + 2] = u.z + v.z;
        }
    }
    if (t == 0) {
        float e = 0.f;
        #pragma unroll
        for (int w = 0; w < FBLK/32; w++) e += s_f[w].w;
        g_part[blockIdx.x] = e;
        __threadfence();
        unsigned int d = atomicAdd(&g_done, 1u);
        s_flag = (d == gridDim.x - 1) ? 1 : 0;
    }
    __syncthreads();

    // last block: reduce partials, write energy, reset scratch state
    if (s_flag) {
        __threadfence();
        __shared__ float s_red[FBLK];
        int nb = gridDim.x;
        float acc = 0.f;
        for (int k = t; k < nb; k += FBLK) acc += g_part[k];
        s_red[t] = acc;
        __syncthreads();
        for (int o = FBLK/2; o > 0; o >>= 1) {
            if (t < o) s_red[t] += s_red[t + o];
            __syncthreads();
        }
        if (t == 0) {
            out[0] = 0.5f * s_red[0];
            g_done = 0u;
        }
        for (int k = t; k < NCMAX; k += FBLK) g_count[k] = 0;
    }
}

// ---------------- launch ----------------
extern "C" void kernel_launch(void* const* d_in, const int* in_sizes, int n_in,
                              void* d_out, int out_size) {
    const float* pos  = (const float*)d_in[0];
    const float* cell = (const float*)d_in[1];
    const float* sig  = (const float*)d_in[2];
    const float* eps  = (const float*)d_in[3];
    const float* alp  = (const float*)d_in[4];
    const int*   spec = (const int*)  d_in[5];
    int n  = in_sizes[5];
    int ss = in_sizes[2];
    int S = 1; while (S*S < ss) S++;
    float* out = (float*)d_out;

    k_bin<<<(n + 127)/128, 128>>>(pos, cell, sig, eps, alp, spec, n, S);
    int nslots = 2 * n;                       // 2 half-warps per atom
    k_force<<<(nslots + FBLK/32 - 1)/(FBLK/32), FBLK>>>(out, n, S);
}